// round 3
// baseline (speedup 1.0000x reference)
#include <cuda_runtime.h>
#include <cuda_bf16.h>
#include <math.h>

#define NMAX 50000
#define EMAX 1600000
#define FIN  128
#define FOUT 64
#define ALPHA 0.2f

// ---------------- scratch (device globals; no allocation) ----------------
__device__ float g_h[NMAX * FOUT];       // h = input @ W
__device__ float g_hcol[NMAX];           // h . a1l
__device__ float g_ha2r[NMAX];           // h . a2r
__device__ float g_pha1r[NMAX];          // p_h . (W a1r)
__device__ float g_nha2l[NMAX];          // new_h . (W a2l)
__device__ float g_ecsm[NMAX];           // col softmax workspace/result
__device__ float g_segmax[NMAX];
__device__ float g_segsum[NMAX];
__device__ float g_erowsum[NMAX];
__device__ float g_edge_e[EMAX];         // ee in original edge order (for att)
__device__ float g_eep[EMAX];            // ee permuted (dst-grouped)
__device__ int   g_srcp[EMAX];           // src permuted (dst-grouped)
__device__ int   g_cnt[NMAX];
__device__ int   g_off[NMAX + 1];
__device__ int   g_head[NMAX];
__device__ float g_v2[FIN], g_v3[FIN];   // W@a1r, W@a2l

// ---------------- small vectors: v2 = W @ a1r, v3 = W @ a2l ----------------
__global__ void k_vec(const float* __restrict__ W,
                      const float* __restrict__ a1,
                      const float* __restrict__ a2) {
    int k = threadIdx.x;  // 128 threads
    float s2 = 0.f, s3 = 0.f;
#pragma unroll 8
    for (int j = 0; j < FOUT; j++) {
        float w = W[k * FOUT + j];
        s2 += w * a1[FOUT + j];
        s3 += w * a2[j];
    }
    g_v2[k] = s2; g_v3[k] = s3;
}

// ---------------- zeroing (graph-replay safe reset) ----------------
__global__ void k_zero(int n) {
    int i = blockIdx.x * blockDim.x + threadIdx.x;
    if (i < n) {
        g_segmax[i] = 0.f;
        g_segsum[i] = 0.f;
        g_cnt[i] = 0;
    }
}

// ---------------- GEMM: h = input @ W (N x 128 x 64) ----------------
// 128 threads; tile 128 rows x 64 cols; thread computes 8x8; K chunk = 32.
__global__ void __launch_bounds__(128)
k_gemm(const float* __restrict__ X, const float* __restrict__ W, int n) {
    __shared__ float Xs[32][128];   // [k][row]  16 KB
    __shared__ float Ws[32][FOUT];  // [k][col]   8 KB
    int tid = threadIdx.x;
    int cg = tid & 7;        // col group: cols cg*8 .. +7
    int rg = tid >> 3;       // row group: rows rg*8 .. +7
    long row0 = (long)blockIdx.x * 128;
    float acc[8][8] = {};

    for (int kb = 0; kb < FIN; kb += 32) {
        // stage W chunk: 32x64 = 512 float4
        for (int i = tid; i < 512; i += 128)
            ((float4*)Ws)[i] = ((const float4*)(W + (long)kb * FOUT))[i];
        // stage X chunk transposed: thread owns one row
        {
            long row = row0 + tid;
            if (row < n) {
                const float4* src = (const float4*)(X + row * FIN + kb);
#pragma unroll
                for (int j = 0; j < 8; j++) {
                    float4 v = src[j];
                    Xs[j * 4 + 0][tid] = v.x;
                    Xs[j * 4 + 1][tid] = v.y;
                    Xs[j * 4 + 2][tid] = v.z;
                    Xs[j * 4 + 3][tid] = v.w;
                }
            } else {
#pragma unroll
                for (int j = 0; j < 32; j++) Xs[j][tid] = 0.f;
            }
        }
        __syncthreads();
#pragma unroll
        for (int k = 0; k < 32; k++) {
            float4 xa = *(const float4*)&Xs[k][rg * 8];
            float4 xb = *(const float4*)&Xs[k][rg * 8 + 4];
            float4 wa = *(const float4*)&Ws[k][cg * 8];
            float4 wb = *(const float4*)&Ws[k][cg * 8 + 4];
            float xr[8] = {xa.x, xa.y, xa.z, xa.w, xb.x, xb.y, xb.z, xb.w};
            float wc[8] = {wa.x, wa.y, wa.z, wa.w, wb.x, wb.y, wb.z, wb.w};
#pragma unroll
            for (int r = 0; r < 8; r++)
#pragma unroll
                for (int c = 0; c < 8; c++)
                    acc[r][c] += xr[r] * wc[c];
        }
        __syncthreads();
    }
#pragma unroll
    for (int r = 0; r < 8; r++) {
        long row = row0 + rg * 8 + r;
        if (row < n) {
            float4 o0 = make_float4(acc[r][0], acc[r][1], acc[r][2], acc[r][3]);
            float4 o1 = make_float4(acc[r][4], acc[r][5], acc[r][6], acc[r][7]);
            float4* dst = (float4*)(g_h + row * FOUT + cg * 8);
            dst[0] = o0; dst[1] = o1;
        }
    }
}

// ---------------- hcol/ha2r from g_h: one warp per row ----------------
__global__ void k_hdots(const float* __restrict__ a1,
                        const float* __restrict__ a2, int n) {
    int w = (blockIdx.x * blockDim.x + threadIdx.x) >> 5;
    int lane = threadIdx.x & 31;
    if (w >= n) return;
    float2 hv = ((const float2*)(g_h + (long)w * FOUT))[lane];
    float2 a1l = ((const float2*)a1)[lane];
    float2 a2r = ((const float2*)(a2 + FOUT))[lane];
    float s1 = hv.x * a1l.x + hv.y * a1l.y;
    float s4 = hv.x * a2r.x + hv.y * a2r.y;
#pragma unroll
    for (int o = 16; o > 0; o >>= 1) {
        s1 += __shfl_down_sync(0xFFFFFFFFu, s1, o);
        s4 += __shfl_down_sync(0xFFFFFFFFu, s4, o);
    }
    if (lane == 0) { g_hcol[w] = s1; g_ha2r[w] = s4; }
}

// ---------------- per-row dot products: pha1r, nha2l ----------------
__global__ void k_dots(const float* __restrict__ P,
                       const float* __restrict__ NH, int n) {
    int w = (blockIdx.x * blockDim.x + threadIdx.x) >> 5;
    int lane = threadIdx.x & 31;
    if (w >= n) return;
    float4 pv = ((const float4*)(P + (long)w * FIN))[lane];
    float4 nv = ((const float4*)(NH + (long)w * FIN))[lane];
    float4 v2 = ((const float4*)g_v2)[lane];
    float4 v3 = ((const float4*)g_v3)[lane];
    float s2 = pv.x * v2.x + pv.y * v2.y + pv.z * v2.z + pv.w * v2.w;
    float s3 = nv.x * v3.x + nv.y * v3.y + nv.z * v3.z + nv.w * v3.w;
#pragma unroll
    for (int o = 16; o > 0; o >>= 1) {
        s2 += __shfl_down_sync(0xFFFFFFFFu, s2, o);
        s3 += __shfl_down_sync(0xFFFFFFFFu, s3, o);
    }
    if (lane == 0) { g_pha1r[w] = s2; g_nha2l[w] = s3; }
}

// ---------------- column softmax passes ----------------
__global__ void k_col1(const int* __restrict__ edge_col0,
                       const int* __restrict__ row_i, int n) {
    int i = blockIdx.x * blockDim.x + threadIdx.x;
    if (i >= n) return;
    float cs = g_hcol[edge_col0[i]] + g_pha1r[i];
    float lr = cs > 0.f ? cs : ALPHA * cs;
    float e = expf(-lr);
    g_ecsm[i] = e;
    atomicMax((int*)&g_segmax[row_i[i]], __float_as_int(e));  // e > 0 always
}
__global__ void k_col2(const int* __restrict__ row_i, int n) {
    int i = blockIdx.x * blockDim.x + threadIdx.x;
    if (i >= n) return;
    float ex = expf(g_ecsm[i] - g_segmax[row_i[i]]);
    g_ecsm[i] = ex;
    atomicAdd(&g_segsum[row_i[i]], ex);
}
__global__ void k_col3(const int* __restrict__ row_i, int n) {
    int i = blockIdx.x * blockDim.x + threadIdx.x;
    if (i >= n) return;
    g_ecsm[i] = g_ecsm[i] / (g_segsum[row_i[i]] + 1e-16f);
}

// ---------------- CSR build: histogram -> scan -> permute ----------------
__global__ void k_hist(const int* __restrict__ edge0, int E) {
    int e = blockIdx.x * blockDim.x + threadIdx.x;
    if (e < E) atomicAdd(&g_cnt[edge0[e]], 1);
}

__global__ void k_scan(int n, int E) {  // single block, 1024 threads
    __shared__ int sm[1024];
    int tid = threadIdx.x;
    int CH = (n + 1023) >> 10;
    int lo = tid * CH;
    int hi = lo + CH; if (hi > n) hi = n;
    int s = 0;
    for (int i = lo; i < hi; i++) s += g_cnt[i];
    sm[tid] = s;
    __syncthreads();
    for (int off = 1; off < 1024; off <<= 1) {
        int v = (tid >= off) ? sm[tid - off] : 0;
        __syncthreads();
        sm[tid] += v;
        __syncthreads();
    }
    int run = (tid > 0) ? sm[tid - 1] : 0;
    for (int i = lo; i < hi; i++) {
        int c = g_cnt[i];
        g_off[i] = run;
        g_head[i] = run;
        run += c;
    }
    if (tid == 0) g_off[n] = E;
}

// edge scores + scatter into dst-grouped arrays
__global__ void k_edge1(const int* __restrict__ edge0,
                        const int* __restrict__ edge1,
                        const int* __restrict__ row_resort, int E) {
    int e = blockIdx.x * blockDim.x + threadIdx.x;
    if (e >= E) return;
    int dst = edge0[e];
    int src = edge1[e];
    int rr = row_resort[e];
    float rs = g_nha2l[rr] + g_ha2r[src];
    float lr = rs > 0.f ? rs : ALPHA * rs;
    float ee = expf(-lr) * g_ecsm[rr];
    g_edge_e[e] = ee;
    int pos = atomicAdd(&g_head[dst], 1);
    g_srcp[pos] = src;
    g_eep[pos] = ee;
}

// ---------------- aggregation: warp per dst, fused finalize ----------------
__global__ void k_aggr(float* __restrict__ out, int n) {
    int w = (blockIdx.x * blockDim.x + threadIdx.x) >> 5;
    int lane = threadIdx.x & 31;
    if (w >= n) return;
    int j = g_off[w];
    int end = g_off[w + 1];
    float ax = 0.f, ay = 0.f, es = 0.f;
    for (; j + 2 <= end; j += 2) {
        int s0 = g_srcp[j], s1 = g_srcp[j + 1];
        float e0 = g_eep[j], e1 = g_eep[j + 1];
        float2 h0 = ((const float2*)(g_h + (long)s0 * FOUT))[lane];
        float2 h1 = ((const float2*)(g_h + (long)s1 * FOUT))[lane];
        ax += e0 * h0.x + e1 * h1.x;
        ay += e0 * h0.y + e1 * h1.y;
        es += e0 + e1;
    }
    if (j < end) {
        int s0 = g_srcp[j];
        float e0 = g_eep[j];
        float2 h0 = ((const float2*)(g_h + (long)s0 * FOUT))[lane];
        ax += e0 * h0.x; ay += e0 * h0.y; es += e0;
    }
    if (lane == 0) g_erowsum[w] = es;
    float inv = (es == 0.f) ? 1.f : 1.f / es;
    float2 v;
    v.x = ax * inv; v.y = ay * inv;
    v.x = v.x > 0.f ? v.x : expm1f(v.x);
    v.y = v.y > 0.f ? v.y : expm1f(v.y);
    ((float2*)(out + (long)w * FOUT))[lane] = v;
}

// ---------------- tail: attention + edge copy ----------------
__global__ void k_tail(const int* __restrict__ edge,
                       float* __restrict__ out_edges,
                       float* __restrict__ out_att, int E) {
    int e = blockIdx.x * blockDim.x + threadIdx.x;
    if (e >= E) return;
    int dst = edge[e];
    int src = edge[E + e];
    out_edges[e] = (float)dst;
    out_edges[E + e] = (float)src;
    float s = g_erowsum[dst];
    if (s == 0.f) s = 1.f;
    out_att[e] = g_edge_e[e] / s;
}

extern "C" void kernel_launch(void* const* d_in, const int* in_sizes, int n_in,
                              void* d_out, int out_size) {
    const float* input      = (const float*)d_in[0];
    const float* p_h        = (const float*)d_in[1];
    const float* new_h      = (const float*)d_in[2];
    const int*   edge       = (const int*)d_in[3];
    const int*   edge_col   = (const int*)d_in[4];
    const int*   row_i      = (const int*)d_in[5];
    const int*   row_resort = (const int*)d_in[6];
    const float* W          = (const float*)d_in[8];
    const float* a1         = (const float*)d_in[9];
    const float* a2         = (const float*)d_in[10];

    int N = in_sizes[0] / FIN;
    int E = in_sizes[3] / 2;
    const int* edge0 = edge;
    const int* edge1 = edge + E;
    float* out = (float*)d_out;

    long n64 = (long)N * FOUT;
    int full = (out_size >= (int)(n64 + 2L * E + E)) ? 1 : 0;
    float* out_edges = full ? out + n64 : nullptr;
    float* out_att   = full ? out + n64 + 2L * E : nullptr;

    const int T = 256;
    k_zero<<<(N + T - 1) / T, T>>>(N);
    k_vec<<<1, 128>>>(W, a1, a2);
    k_gemm<<<(N + 127) / 128, 128>>>(input, W, N);
    k_hdots<<<(N * 32 + T - 1) / T, T>>>(a1, a2, N);
    k_dots<<<(N * 32 + T - 1) / T, T>>>(p_h, new_h, N);

    k_col1<<<(N + T - 1) / T, T>>>(edge_col, row_i, N);
    k_col2<<<(N + T - 1) / T, T>>>(row_i, N);
    k_col3<<<(N + T - 1) / T, T>>>(row_i, N);

    k_hist<<<(E + T - 1) / T, T>>>(edge0, E);
    k_scan<<<1, 1024>>>(N, E);
    k_edge1<<<(E + T - 1) / T, T>>>(edge0, edge1, row_resort, E);

    k_aggr<<<(N * 32 + T - 1) / T, T>>>(out, N);
    if (full) {
        k_tail<<<(E + T - 1) / T, T>>>(edge, out_edges, out_att, E);
    }
}

// round 4
// speedup vs baseline: 1.0168x; 1.0168x over previous
#include <cuda_runtime.h>
#include <cuda_bf16.h>
#include <math.h>

#define NMAX 50000
#define EMAX 1600000
#define FIN  128
#define FOUT 64
#define ALPHA 0.2f

// ---------------- scratch (device globals; no allocation) ----------------
__device__ float g_h[NMAX * FOUT];       // h = input @ W
__device__ float g_hcol[NMAX];           // h . a1l  (= input . (W a1l))
__device__ float g_ha2r[NMAX];           // h . a2r
__device__ float g_pha1r[NMAX];          // p_h . (W a1r)
__device__ float g_nha2l[NMAX];          // new_h . (W a2l)
__device__ float g_ecsm[NMAX];           // col softmax workspace/result
__device__ float g_segmax[NMAX];
__device__ float g_segsum[NMAX];
__device__ float g_erowsum[NMAX];
__device__ float g_edge_e[EMAX];         // ee in original edge order (for att)
__device__ float2 g_pair[EMAX];          // (ee, src-as-float-bits), dst-grouped
__device__ int   g_cnt[NMAX];
__device__ int   g_off[NMAX + 1];
__device__ int   g_head[NMAX];
__device__ float g_v1[FIN], g_v2[FIN], g_v3[FIN], g_v4[FIN];

// ---------------- small vectors: v = W @ a-halves (R1 version) ----------------
__global__ void k_vec(const float* __restrict__ W,
                      const float* __restrict__ a1,
                      const float* __restrict__ a2) {
    int k = threadIdx.x;  // 128 threads
    float s1 = 0.f, s2 = 0.f, s3 = 0.f, s4 = 0.f;
#pragma unroll 8
    for (int j = 0; j < FOUT; j++) {
        float w = W[k * FOUT + j];
        s1 += w * a1[j];
        s2 += w * a1[FOUT + j];
        s3 += w * a2[j];
        s4 += w * a2[FOUT + j];
    }
    g_v1[k] = s1; g_v2[k] = s2; g_v3[k] = s3; g_v4[k] = s4;
}

// ---------------- zeroing (graph-replay safe reset) ----------------
__global__ void k_zero(int n) {
    int i = blockIdx.x * blockDim.x + threadIdx.x;
    if (i < n) {
        g_segmax[i] = 0.f;
        g_segsum[i] = 0.f;
        g_cnt[i] = 0;
    }
}

// ---------------- GEMM: h = input @ W (N x 128 x 64)  [R1 version, 39us] ----
__global__ void k_gemm(const float* __restrict__ X,
                       const float* __restrict__ W, int n) {
    __shared__ float Ws[FIN * FOUT];      // 32 KB
    __shared__ float Xs[32 * FIN];        // 16 KB
    int tid = threadIdx.x;
    for (int i = tid; i < FIN * FOUT / 4; i += 256)
        ((float4*)Ws)[i] = ((const float4*)W)[i];
    long row0 = (long)blockIdx.x * 32;
    int rem = n - (int)row0; if (rem > 32) rem = 32;
    const float4* xsrc = (const float4*)(X + row0 * FIN);
    for (int i = tid; i < rem * (FIN / 4); i += 256)
        ((float4*)Xs)[i] = xsrc[i];
    __syncthreads();
    int w = tid >> 5, lane = tid & 31;
    float acc[4][2] = {};
#pragma unroll 4
    for (int k = 0; k < FIN; k++) {
        float2 wv = ((const float2*)(Ws + k * FOUT))[lane];
#pragma unroll
        for (int r = 0; r < 4; r++) {
            float xk = Xs[(w * 4 + r) * FIN + k];
            acc[r][0] += xk * wv.x;
            acc[r][1] += xk * wv.y;
        }
    }
#pragma unroll
    for (int r = 0; r < 4; r++) {
        long row = row0 + w * 4 + r;
        if (row < n) {
            float2 o; o.x = acc[r][0]; o.y = acc[r][1];
            ((float2*)(g_h + row * FOUT))[lane] = o;
        }
    }
}

// ---------------- per-row dot products (R1 version) ----------------
__global__ void k_dots(const float* __restrict__ X,
                       const float* __restrict__ P,
                       const float* __restrict__ NH, int n) {
    int warp = (blockIdx.x * blockDim.x + threadIdx.x) >> 5;
    int lane = threadIdx.x & 31;
    if (warp >= n) return;
    float4 xv = ((const float4*)(X + (long)warp * FIN))[lane];
    float4 pv = ((const float4*)(P + (long)warp * FIN))[lane];
    float4 nv = ((const float4*)(NH + (long)warp * FIN))[lane];
    float4 v1 = ((const float4*)g_v1)[lane];
    float4 v2 = ((const float4*)g_v2)[lane];
    float4 v3 = ((const float4*)g_v3)[lane];
    float4 v4 = ((const float4*)g_v4)[lane];
    float s_hcol = xv.x * v1.x + xv.y * v1.y + xv.z * v1.z + xv.w * v1.w;
    float s_ha2r = xv.x * v4.x + xv.y * v4.y + xv.z * v4.z + xv.w * v4.w;
    float s_pha1 = pv.x * v2.x + pv.y * v2.y + pv.z * v2.z + pv.w * v2.w;
    float s_nha2 = nv.x * v3.x + nv.y * v3.y + nv.z * v3.z + nv.w * v3.w;
#pragma unroll
    for (int o = 16; o > 0; o >>= 1) {
        s_hcol += __shfl_down_sync(0xFFFFFFFFu, s_hcol, o);
        s_ha2r += __shfl_down_sync(0xFFFFFFFFu, s_ha2r, o);
        s_pha1 += __shfl_down_sync(0xFFFFFFFFu, s_pha1, o);
        s_nha2 += __shfl_down_sync(0xFFFFFFFFu, s_nha2, o);
    }
    if (lane == 0) {
        g_hcol[warp] = s_hcol;
        g_ha2r[warp] = s_ha2r;
        g_pha1r[warp] = s_pha1;
        g_nha2l[warp] = s_nha2;
    }
}

// ---------------- column softmax passes (R1 version) ----------------
__global__ void k_col1(const int* __restrict__ edge_col0,
                       const int* __restrict__ row_i, int n) {
    int i = blockIdx.x * blockDim.x + threadIdx.x;
    if (i >= n) return;
    float cs = g_hcol[edge_col0[i]] + g_pha1r[i];
    float lr = cs > 0.f ? cs : ALPHA * cs;
    float e = expf(-lr);
    g_ecsm[i] = e;
    atomicMax((int*)&g_segmax[row_i[i]], __float_as_int(e));  // e > 0 always
}
__global__ void k_col2(const int* __restrict__ row_i, int n) {
    int i = blockIdx.x * blockDim.x + threadIdx.x;
    if (i >= n) return;
    float ex = expf(g_ecsm[i] - g_segmax[row_i[i]]);
    g_ecsm[i] = ex;
    atomicAdd(&g_segsum[row_i[i]], ex);
}
__global__ void k_col3(const int* __restrict__ row_i, int n) {
    int i = blockIdx.x * blockDim.x + threadIdx.x;
    if (i >= n) return;
    g_ecsm[i] = g_ecsm[i] / (g_segsum[row_i[i]] + 1e-16f);
}

// ---------------- CSR build: histogram -> scan ----------------
__global__ void k_hist(const int* __restrict__ edge0, int E) {
    int e = blockIdx.x * blockDim.x + threadIdx.x;
    if (e < E) atomicAdd(&g_cnt[edge0[e]], 1);
}

__global__ void k_scan(int n, int E) {  // single block, 1024 threads
    __shared__ int sm[1024];
    int tid = threadIdx.x;
    int CH = (n + 1023) >> 10;
    int lo = tid * CH;
    int hi = lo + CH; if (hi > n) hi = n;
    int s = 0;
    for (int i = lo; i < hi; i++) s += g_cnt[i];
    sm[tid] = s;
    __syncthreads();
    for (int off = 1; off < 1024; off <<= 1) {
        int v = (tid >= off) ? sm[tid - off] : 0;
        __syncthreads();
        sm[tid] += v;
        __syncthreads();
    }
    int run = (tid > 0) ? sm[tid - 1] : 0;
    for (int i = lo; i < hi; i++) {
        int c = g_cnt[i];
        g_off[i] = run;
        g_head[i] = run;
        run += c;
    }
    if (tid == 0) g_off[n] = E;
}

// ---------------- edge scores + permute into dst-grouped pairs ----------------
__global__ void k_edge1(const int* __restrict__ edge0,
                        const int* __restrict__ edge1,
                        const int* __restrict__ row_resort, int E) {
    int e = blockIdx.x * blockDim.x + threadIdx.x;
    if (e >= E) return;
    int dst = edge0[e];
    int src = edge1[e];
    int rr = row_resort[e];
    float rs = g_nha2l[rr] + g_ha2r[src];
    float lr = rs > 0.f ? rs : ALPHA * rs;
    float ee = expf(-lr) * g_ecsm[rr];
    g_edge_e[e] = ee;
    int pos = atomicAdd(&g_head[dst], 1);
    g_pair[pos] = make_float2(ee, __int_as_float(src));
}

// ---------------- aggregation: warp per dst, half-warp per edge, unroll 2 ----
// 4 independent 256B h-row gathers in flight per warp. Fused rowsum + elu.
__global__ void k_aggr(float* __restrict__ out, int n) {
    int w = (blockIdx.x * blockDim.x + threadIdx.x) >> 5;
    int lane = threadIdx.x & 31;
    if (w >= n) return;
    int half = lane >> 4;   // 0 or 1
    int t = lane & 15;      // 16B segment of the 256B row
    int beg = g_off[w], end = g_off[w + 1];
    float4 acc = make_float4(0.f, 0.f, 0.f, 0.f);
    float es = 0.f;
    int j = beg + half;     // this half-warp handles edges beg+half, +2, +4, ...
    // unrolled by 2: edges j and j+2 in flight simultaneously
    for (; j + 2 < end; j += 4) {
        float2 p0 = g_pair[j];
        float2 p1 = g_pair[j + 2];
        int s0 = __float_as_int(p0.y);
        int s1 = __float_as_int(p1.y);
        float4 h0 = *(const float4*)(g_h + (long)s0 * FOUT + t * 4);
        float4 h1 = *(const float4*)(g_h + (long)s1 * FOUT + t * 4);
        acc.x += p0.x * h0.x + p1.x * h1.x;
        acc.y += p0.x * h0.y + p1.x * h1.y;
        acc.z += p0.x * h0.z + p1.x * h1.z;
        acc.w += p0.x * h0.w + p1.x * h1.w;
        es += p0.x + p1.x;
    }
    if (j < end) {
        float2 p0 = g_pair[j];
        int s0 = __float_as_int(p0.y);
        float4 h0 = *(const float4*)(g_h + (long)s0 * FOUT + t * 4);
        acc.x += p0.x * h0.x;
        acc.y += p0.x * h0.y;
        acc.z += p0.x * h0.z;
        acc.w += p0.x * h0.w;
        es += p0.x;
    }
    // combine halves (lane t and lane t+16 cover the same 16B output segment)
    acc.x += __shfl_xor_sync(0xFFFFFFFFu, acc.x, 16);
    acc.y += __shfl_xor_sync(0xFFFFFFFFu, acc.y, 16);
    acc.z += __shfl_xor_sync(0xFFFFFFFFu, acc.z, 16);
    acc.w += __shfl_xor_sync(0xFFFFFFFFu, acc.w, 16);
    // es: each half accumulated ee once per lane (all 16 lanes of a half hold
    // the same es). Combine the two halves, take from lane 0's value.
    float es_other = __shfl_xor_sync(0xFFFFFFFFu, es, 16);
    es += es_other;
    if (lane == 0) g_erowsum[w] = es;
    float inv = (es == 0.f) ? 1.f : 1.f / es;
    if (half == 0) {
        float4 v;
        v.x = acc.x * inv; v.y = acc.y * inv;
        v.z = acc.z * inv; v.w = acc.w * inv;
        v.x = v.x > 0.f ? v.x : expm1f(v.x);
        v.y = v.y > 0.f ? v.y : expm1f(v.y);
        v.z = v.z > 0.f ? v.z : expm1f(v.z);
        v.w = v.w > 0.f ? v.w : expm1f(v.w);
        ((float4*)(out + (long)w * FOUT))[t] = v;
    }
}

// ---------------- tail: attention + edge copy ----------------
__global__ void k_tail(const int* __restrict__ edge,
                       float* __restrict__ out_edges,
                       float* __restrict__ out_att, int E) {
    int e = blockIdx.x * blockDim.x + threadIdx.x;
    if (e >= E) return;
    int dst = edge[e];
    int src = edge[E + e];
    out_edges[e] = (float)dst;
    out_edges[E + e] = (float)src;
    float s = g_erowsum[dst];
    if (s == 0.f) s = 1.f;
    out_att[e] = g_edge_e[e] / s;
}

extern "C" void kernel_launch(void* const* d_in, const int* in_sizes, int n_in,
                              void* d_out, int out_size) {
    const float* input      = (const float*)d_in[0];
    const float* p_h        = (const float*)d_in[1];
    const float* new_h      = (const float*)d_in[2];
    const int*   edge       = (const int*)d_in[3];
    const int*   edge_col   = (const int*)d_in[4];
    const int*   row_i      = (const int*)d_in[5];
    const int*   row_resort = (const int*)d_in[6];
    const float* W          = (const float*)d_in[8];
    const float* a1         = (const float*)d_in[9];
    const float* a2         = (const float*)d_in[10];

    int N = in_sizes[0] / FIN;
    int E = in_sizes[3] / 2;
    const int* edge0 = edge;
    const int* edge1 = edge + E;
    float* out = (float*)d_out;

    long n64 = (long)N * FOUT;
    int full = (out_size >= (int)(n64 + 2L * E + E)) ? 1 : 0;
    float* out_edges = full ? out + n64 : nullptr;
    float* out_att   = full ? out + n64 + 2L * E : nullptr;

    const int T = 256;
    k_zero<<<(N + T - 1) / T, T>>>(N);
    k_vec<<<1, 128>>>(W, a1, a2);
    k_gemm<<<(N + 31) / 32, 256>>>(input, W, N);
    k_dots<<<(N * 32 + T - 1) / T, T>>>(input, p_h, new_h, N);

    k_col1<<<(N + T - 1) / T, T>>>(edge_col, row_i, N);
    k_col2<<<(N + T - 1) / T, T>>>(row_i, N);
    k_col3<<<(N + T - 1) / T, T>>>(row_i, N);

    k_hist<<<(E + T - 1) / T, T>>>(edge0, E);
    k_scan<<<1, 1024>>>(N, E);
    k_edge1<<<(E + T - 1) / T, T>>>(edge0, edge1, row_resort, E);

    k_aggr<<<(N * 32 + T - 1) / T, T>>>(out, N);
    if (full) {
        k_tail<<<(E + T - 1) / T, T>>>(edge, out_edges, out_att, E);
    }
}

// round 5
// speedup vs baseline: 1.0995x; 1.0813x over previous
#include <cuda_runtime.h>
#include <cuda_fp16.h>
#include <math.h>

#define NMAX 50000
#define EMAX 1600000
#define FIN  128
#define FOUT 64
#define ALPHA 0.2f

// ---------------- scratch (device globals; no allocation) ----------------
__device__ __half g_h16[NMAX * FOUT];    // h = input @ W  (fp16 for the gather)
__device__ float g_hprime[NMAX * FOUT];  // segment sum accumulator (fp32)
__device__ float g_hcol[NMAX];           // h . a1l  (= input . (W a1l))
__device__ float g_ha2r[NMAX];           // h . a2r
__device__ float g_pha1r[NMAX];          // p_h . (W a1r)
__device__ float g_nha2l[NMAX];          // new_h . (W a2l)
__device__ float g_ecsm[NMAX];           // edge_col_e -> ex -> softmax result
__device__ float g_segmax[NMAX];
__device__ float g_segsum[NMAX];
__device__ float g_erowsum[NMAX];
__device__ float g_einv[NMAX];
__device__ float g_edge_e[EMAX];
__device__ float g_v1[FIN], g_v2[FIN], g_v3[FIN], g_v4[FIN];

// ---------------- small vectors: v = W @ a-halves ----------------
__global__ void k_vec(const float* __restrict__ W,
                      const float* __restrict__ a1,
                      const float* __restrict__ a2) {
    int k = threadIdx.x;  // 128 threads
    float s1 = 0.f, s2 = 0.f, s3 = 0.f, s4 = 0.f;
#pragma unroll 8
    for (int j = 0; j < FOUT; j++) {
        float w = W[k * FOUT + j];
        s1 += w * a1[j];
        s2 += w * a1[FOUT + j];
        s3 += w * a2[j];
        s4 += w * a2[FOUT + j];
    }
    g_v1[k] = s1; g_v2[k] = s2; g_v3[k] = s3; g_v4[k] = s4;
}

// ---------------- zeroing (graph-replay safe reset) ----------------
__global__ void k_zero_n(int n) {
    int i = blockIdx.x * blockDim.x + threadIdx.x;
    if (i < n) {
        g_segmax[i] = 0.f;
        g_segsum[i] = 0.f;
        g_erowsum[i] = 0.f;
    }
}
__global__ void k_zero_hp(int n4) {  // n4 = N*FOUT/4
    int i = blockIdx.x * blockDim.x + threadIdx.x;
    if (i < n4) ((float4*)g_hprime)[i] = make_float4(0.f, 0.f, 0.f, 0.f);
}

// ---------------- GEMM: h = input @ W (N x 128 x 64) ----------------
// R1 version; epilogue converts to fp16.
__global__ void k_gemm(const float* __restrict__ X,
                       const float* __restrict__ W, int n) {
    __shared__ float Ws[FIN * FOUT];      // 32 KB
    __shared__ float Xs[32 * FIN];        // 16 KB
    int tid = threadIdx.x;
    for (int i = tid; i < FIN * FOUT / 4; i += 256)
        ((float4*)Ws)[i] = ((const float4*)W)[i];
    long row0 = (long)blockIdx.x * 32;
    int rem = n - (int)row0; if (rem > 32) rem = 32;
    const float4* xsrc = (const float4*)(X + row0 * FIN);
    for (int i = tid; i < rem * (FIN / 4); i += 256)
        ((float4*)Xs)[i] = xsrc[i];
    __syncthreads();
    int w = tid >> 5, lane = tid & 31;
    float acc[4][2] = {};
#pragma unroll 4
    for (int k = 0; k < FIN; k++) {
        float2 wv = ((const float2*)(Ws + k * FOUT))[lane];
#pragma unroll
        for (int r = 0; r < 4; r++) {
            float xk = Xs[(w * 4 + r) * FIN + k];
            acc[r][0] += xk * wv.x;
            acc[r][1] += xk * wv.y;
        }
    }
#pragma unroll
    for (int r = 0; r < 4; r++) {
        long row = row0 + w * 4 + r;
        if (row < n) {
            __half2 o = __floats2half2_rn(acc[r][0], acc[r][1]);
            ((__half2*)(g_h16 + row * FOUT))[lane] = o;
        }
    }
}

// ---------------- per-row dot products (matrix-vector) ----------------
__global__ void k_dots(const float* __restrict__ X,
                       const float* __restrict__ P,
                       const float* __restrict__ NH, int n) {
    int warp = (blockIdx.x * blockDim.x + threadIdx.x) >> 5;
    int lane = threadIdx.x & 31;
    if (warp >= n) return;
    float4 xv = ((const float4*)(X + (long)warp * FIN))[lane];
    float4 pv = ((const float4*)(P + (long)warp * FIN))[lane];
    float4 nv = ((const float4*)(NH + (long)warp * FIN))[lane];
    float4 v1 = ((const float4*)g_v1)[lane];
    float4 v2 = ((const float4*)g_v2)[lane];
    float4 v3 = ((const float4*)g_v3)[lane];
    float4 v4 = ((const float4*)g_v4)[lane];
    float s_hcol = xv.x * v1.x + xv.y * v1.y + xv.z * v1.z + xv.w * v1.w;
    float s_ha2r = xv.x * v4.x + xv.y * v4.y + xv.z * v4.z + xv.w * v4.w;
    float s_pha1 = pv.x * v2.x + pv.y * v2.y + pv.z * v2.z + pv.w * v2.w;
    float s_nha2 = nv.x * v3.x + nv.y * v3.y + nv.z * v3.z + nv.w * v3.w;
#pragma unroll
    for (int o = 16; o > 0; o >>= 1) {
        s_hcol += __shfl_down_sync(0xFFFFFFFFu, s_hcol, o);
        s_ha2r += __shfl_down_sync(0xFFFFFFFFu, s_ha2r, o);
        s_pha1 += __shfl_down_sync(0xFFFFFFFFu, s_pha1, o);
        s_nha2 += __shfl_down_sync(0xFFFFFFFFu, s_nha2, o);
    }
    if (lane == 0) {
        g_hcol[warp] = s_hcol;
        g_ha2r[warp] = s_ha2r;
        g_pha1r[warp] = s_pha1;
        g_nha2l[warp] = s_nha2;
    }
}

// ---------------- column softmax passes ----------------
__global__ void k_col1(const int* __restrict__ edge_col0,
                       const int* __restrict__ row_i, int n) {
    int i = blockIdx.x * blockDim.x + threadIdx.x;
    if (i >= n) return;
    float cs = g_hcol[edge_col0[i]] + g_pha1r[i];
    float lr = cs > 0.f ? cs : ALPHA * cs;
    float e = expf(-lr);
    g_ecsm[i] = e;
    atomicMax((int*)&g_segmax[row_i[i]], __float_as_int(e));  // e > 0 always
}
__global__ void k_col2(const int* __restrict__ row_i, int n) {
    int i = blockIdx.x * blockDim.x + threadIdx.x;
    if (i >= n) return;
    float ex = expf(g_ecsm[i] - g_segmax[row_i[i]]);
    g_ecsm[i] = ex;
    atomicAdd(&g_segsum[row_i[i]], ex);
}
__global__ void k_col3(const int* __restrict__ row_i, int n) {
    int i = blockIdx.x * blockDim.x + threadIdx.x;
    if (i >= n) return;
    g_ecsm[i] = g_ecsm[i] / (g_segsum[row_i[i]] + 1e-16f);
}

// ---------------- edge scores + rowsum ----------------
__global__ void k_edge1(const int* __restrict__ edge0,
                        const int* __restrict__ edge1,
                        const int* __restrict__ row_resort, int E) {
    int e = blockIdx.x * blockDim.x + threadIdx.x;
    if (e >= E) return;
    int rr = row_resort[e];
    float rs = g_nha2l[rr] + g_ha2r[edge1[e]];
    float lr = rs > 0.f ? rs : ALPHA * rs;
    float ee = expf(-lr) * g_ecsm[rr];
    g_edge_e[e] = ee;
    atomicAdd(&g_erowsum[edge0[e]], ee);
}
__global__ void k_rowfix(int n) {
    int i = blockIdx.x * blockDim.x + threadIdx.x;
    if (i >= n) return;
    float s = g_erowsum[i];
    if (s == 0.f) s = 1.f;
    g_einv[i] = 1.f / s;
}

// ---------------- main scatter: h_prime += edge_e * h[edge1] ----------------
// 8 threads per edge: each loads 16B of fp16 (8 halves), expands to fp32,
// issues two red.global.add.v4.f32.
__global__ void k_edge2(const int* __restrict__ edge0,
                        const int* __restrict__ edge1,
                        float* __restrict__ att_out, int E, int write_att) {
    int e = (blockIdx.x * blockDim.x + threadIdx.x) >> 3;
    int t = threadIdx.x & 7;
    if (e >= E) return;
    int dst = edge0[e], src = edge1[e];
    float ee = g_edge_e[e];
    const uint4 hv = *(const uint4*)(g_h16 + (long)src * FOUT + t * 8);
    float2 f0 = __half22float2(*(const __half2*)&hv.x);
    float2 f1 = __half22float2(*(const __half2*)&hv.y);
    float2 f2 = __half22float2(*(const __half2*)&hv.z);
    float2 f3 = __half22float2(*(const __half2*)&hv.w);
    float* dp = g_hprime + (long)dst * FOUT + t * 8;
    asm volatile("red.global.add.v4.f32 [%0], {%1, %2, %3, %4};"
                 :: "l"(__cvta_generic_to_global(dp)),
                    "f"(ee * f0.x), "f"(ee * f0.y), "f"(ee * f1.x), "f"(ee * f1.y)
                 : "memory");
    asm volatile("red.global.add.v4.f32 [%0], {%1, %2, %3, %4};"
                 :: "l"(__cvta_generic_to_global(dp + 4)),
                    "f"(ee * f2.x), "f"(ee * f2.y), "f"(ee * f3.x), "f"(ee * f3.y)
                 : "memory");
    if (t == 0 && write_att) att_out[e] = ee * g_einv[dst];
}

// ---------------- finalize: out = elu(h_prime / e_rowsum) ----------------
__global__ void k_final(float* __restrict__ out, int n) {
    int i4 = blockIdx.x * blockDim.x + threadIdx.x;  // one float4 each
    if (i4 >= n * (FOUT / 4)) return;
    int row = i4 >> 4;
    float inv = g_einv[row];
    float4 v = ((const float4*)g_hprime)[i4];
    v.x *= inv; v.y *= inv; v.z *= inv; v.w *= inv;
    v.x = v.x > 0.f ? v.x : expm1f(v.x);
    v.y = v.y > 0.f ? v.y : expm1f(v.y);
    v.z = v.z > 0.f ? v.z : expm1f(v.z);
    v.w = v.w > 0.f ? v.w : expm1f(v.w);
    ((float4*)out)[i4] = v;
}

// ---------------- copy edge indices to output as float ----------------
__global__ void k_edgecopy(const int* __restrict__ edge, float* __restrict__ out,
                           int n2e) {
    int i = blockIdx.x * blockDim.x + threadIdx.x;
    if (i < n2e) out[i] = (float)edge[i];
}

extern "C" void kernel_launch(void* const* d_in, const int* in_sizes, int n_in,
                              void* d_out, int out_size) {
    const float* input      = (const float*)d_in[0];
    const float* p_h        = (const float*)d_in[1];
    const float* new_h      = (const float*)d_in[2];
    const int*   edge       = (const int*)d_in[3];
    const int*   edge_col   = (const int*)d_in[4];
    const int*   row_i      = (const int*)d_in[5];
    const int*   row_resort = (const int*)d_in[6];
    const float* W          = (const float*)d_in[8];
    const float* a1         = (const float*)d_in[9];
    const float* a2         = (const float*)d_in[10];

    int N = in_sizes[0] / FIN;
    int E = in_sizes[3] / 2;
    const int* edge0 = edge;
    const int* edge1 = edge + E;
    float* out = (float*)d_out;

    long n64 = (long)N * FOUT;
    int full = (out_size >= (int)(n64 + 2L * E + E)) ? 1 : 0;
    float* out_edges = full ? out + n64 : nullptr;
    float* out_att   = full ? out + n64 + 2L * E : out;  // dummy if !full

    const int T = 256;
    // zero scratch (every call: graph replays)
    k_zero_n<<<(N + T - 1) / T, T>>>(N);
    k_zero_hp<<<((N * FOUT / 4) + T - 1) / T, T>>>(N * FOUT / 4);

    k_vec<<<1, 128>>>(W, a1, a2);
    k_gemm<<<(N + 31) / 32, 256>>>(input, W, N);
    k_dots<<<(N * 32 + T - 1) / T, T>>>(input, p_h, new_h, N);

    k_col1<<<(N + T - 1) / T, T>>>(edge_col, row_i, N);
    k_col2<<<(N + T - 1) / T, T>>>(row_i, N);
    k_col3<<<(N + T - 1) / T, T>>>(row_i, N);

    k_edge1<<<(E + T - 1) / T, T>>>(edge0, edge1, row_resort, E);
    k_rowfix<<<(N + T - 1) / T, T>>>(N);

    k_edge2<<<(E * 8 + T - 1) / T, T>>>(edge0, edge1, out_att, E, full);
    k_final<<<((N * FOUT / 4) + T - 1) / T, T>>>(out, N);
    if (full) {
        k_edgecopy<<<(2 * E + T - 1) / T, T>>>(edge, out_edges, 2 * E);
    }
}